// round 12
// baseline (speedup 1.0000x reference)
#include <cuda_runtime.h>
#include <math.h>

#define BB  8
#define NPT 2048
#define NTOT (BB*NPT)
#define HID 256
#define NITER 14

typedef unsigned long long u64;

// ---------------- f32x2 packed helpers (sm_103a) ----------------
__device__ __forceinline__ u64 pk2(float lo, float hi) {
    u64 r; asm("mov.b64 %0,{%1,%2};" : "=l"(r) : "f"(lo), "f"(hi)); return r;
}
__device__ __forceinline__ void up2(u64 v, float& lo, float& hi) {
    asm("mov.b64 {%0,%1},%2;" : "=f"(lo), "=f"(hi) : "l"(v));
}
__device__ __forceinline__ u64 fma2_(u64 a, u64 b, u64 c) {
    u64 r; asm("fma.rn.f32x2 %0,%1,%2,%3;" : "=l"(r) : "l"(a), "l"(b), "l"(c)); return r;
}
__device__ __forceinline__ u64 add2_(u64 a, u64 b) {
    u64 r; asm("add.rn.f32x2 %0,%1,%2;" : "=l"(r) : "l"(a), "l"(b)); return r;
}
__device__ __forceinline__ u64 mul2_(u64 a, u64 b) {
    u64 r; asm("mul.rn.f32x2 %0,%1,%2;" : "=l"(r) : "l"(a), "l"(b)); return r;
}
__device__ __forceinline__ float ex2_(float x) {
    float r; asm("ex2.approx.f32 %0,%1;" : "=f"(r) : "f"(x)); return r;
}

// Packed exp2 on the fma pipe with RANGE-GUARDED scaling.
// 2^a = 2^n * (1 + r*P(r)), n = rni(a) (magic-number), r = a - n.
// The exponent of 2^n is inserted ONLY when bits(b) lies in the valid window
// (n in [-126,127]); every other case (deep underflow n<-126, |a| beyond the
// magic window, negative b) maps to an out-of-range unsigned delta and flushes
// the scale to +0.0f, so the result is exactly 0 regardless of the poly value.
// Upper side (a>127 -> overflow) cannot occur: duality bounds max arg <= ~96.
__device__ __forceinline__ u64 exp2p2(u64 ea, u64 MAG, u64 NMAG,
                                      u64 C6, u64 C5, u64 C4, u64 C3, u64 C2, u64 C1) {
    u64 b  = add2_(ea, MAG);                        // bits = 0x4B400000 + n (in window)
    u64 nf = add2_(b, NMAG);                        // n as float
    u64 r  = add2_(ea, nf ^ 0x8000000080000000ULL); // r = a - n
    u64 p  = fma2_(C6, r, C5);
    p = fma2_(p, r, C4);
    p = fma2_(p, r, C3);
    p = fma2_(p, r, C2);
    p = fma2_(p, r, C1);
    u64 t  = mul2_(p, r);                           // 2^r = 1 + t
    unsigned int bl, bh;
    asm("mov.b64 {%0,%1},%2;" : "=r"(bl), "=r"(bh) : "l"(b));
    unsigned int dl = bl - 0x4B3FFF81u;             // = n + 127 when in window
    unsigned int dh = bh - 0x4B3FFF81u;
    unsigned int sl = (dl <= 254u) ? (dl << 23) : 0u;   // bits of 2^n, else +0.0f
    unsigned int sh = (dh <= 254u) ? (dh << 23) : 0u;
    u64 sc;
    asm("mov.b64 %0,{%1,%2};" : "=l"(sc) : "r"(sl), "r"(sh));
    return fma2_(t, sc, sc);                        // 2^n * (1 + t)  (0 if flushed)
}

// ---------------- persistent scratch ----------------
__device__ float4 g_xp[NTOT];   // noise points packed: (x,y,z,|x|^2)
__device__ float4 g_yp[NTOT];   // x0 points packed:    (x,y,z,|y|^2)
// interleaved pair tiles for k_half reduce side:
//   g_xy*[pair] = (x_{2j}, x_{2j+1}, y_{2j}, y_{2j+1})
//   g_zc*[pair] = (z_{2j}, z_{2j+1}, c_{2j}, c_{2j+1}),  c = phi - 0.5*|p|^2
__device__ float4 g_xyX[NTOT/2], g_zcX[NTOT/2];   // X side (noise)
__device__ float4 g_xyY[NTOT/2], g_zcY[NTOT/2];   // Y side (x0)
__device__ float  g_g[NTOT];
__device__ float  g_std[BB];
__device__ int    g_idx[NTOT];
// j-split partial-sum machinery
__device__ float  g_acc[NTOT];     // per-row partial sum accumulator (zero outside launches)
__device__ int    g_cnt[BB * 64];  // per (batch, rowblock) arrival counter

// ---------------- per-batch std (ddof=1) ----------------
__global__ void k_std(const float* __restrict__ cloud) {
    __shared__ float red[256];
    const int b = blockIdx.x;
    const float* p = cloud + b * NPT * 3;
    const int tid = threadIdx.x;
    float s = 0.f;
    for (int i = tid; i < NPT * 3; i += 256) s += p[i];
    red[tid] = s; __syncthreads();
    for (int o = 128; o > 0; o >>= 1) { if (tid < o) red[tid] += red[tid + o]; __syncthreads(); }
    const float mean = red[0] / (float)(NPT * 3);
    __syncthreads();
    float s2 = 0.f;
    for (int i = tid; i < NPT * 3; i += 256) { float d = p[i] - mean; s2 = fmaf(d, d, s2); }
    red[tid] = s2; __syncthreads();
    for (int o = 128; o > 0; o >>= 1) { if (tid < o) red[tid] += red[tid + o]; __syncthreads(); }
    if (tid == 0) g_std[b] = sqrtf(red[0] / (float)(NPT * 3 - 1));
}

// ---------------- pack points, build interleaved tiles, init folded constants ----------------
__global__ void k_pack(const float* __restrict__ cloud, const float* __restrict__ noise) {
    int i = blockIdx.x * blockDim.x + threadIdx.x;
    if (i >= NTOT) return;
    int b = i >> 11;
    float sd = g_std[b];
    float c0 = cloud[i * 3 + 0] / sd;
    float c1 = cloud[i * 3 + 1] / sd;
    float c2 = cloud[i * 3 + 2] / sd;
    float yn = __fadd_rn(__fadd_rn(__fmul_rn(c0, c0), __fmul_rn(c1, c1)), __fmul_rn(c2, c2));
    g_yp[i] = make_float4(c0, c1, c2, yn);
    float n0 = noise[i * 3 + 0], n1 = noise[i * 3 + 1], n2 = noise[i * 3 + 2];
    float xn = __fadd_rn(__fadd_rn(__fmul_rn(n0, n0), __fmul_rn(n1, n1)), __fmul_rn(n2, n2));
    g_xp[i] = make_float4(n0, n1, n2, xn);

    const int pr = i >> 1, h = i & 1;
    float* fxyX = (float*)g_xyX; float* fzcX = (float*)g_zcX;
    float* fxyY = (float*)g_xyY; float* fzcY = (float*)g_zcY;
    fxyX[pr * 4 + h]     = n0;
    fxyX[pr * 4 + 2 + h] = n1;
    fzcX[pr * 4 + h]     = n2;
    fzcX[pr * 4 + 2 + h] = __fmul_rn(-0.5f, xn);   // phi==0 -> c = -0.5|x|^2
    fxyY[pr * 4 + h]     = c0;
    fxyY[pr * 4 + 2 + h] = c1;
    fzcY[pr * 4 + h]     = c2;
    fzcY[pr * 4 + 2 + h] = __fmul_rn(-0.5f, yn);

    g_acc[i] = 0.f;
    if (i < BB * 64) g_cnt[i] = 0;
}

// log2(1/2048) is exactly -11
#define LOGC2 (-11.0f)
#define LN2F  (0.6931471805599453f)

// ---------------- one Sinkhorn half-update: single pass, duality shift, hybrid exp ----------------
// arg(i,j) = (q_i.p_j + c_j)*ie2 + khat_i,  khat_i = c_row_i*ie2. Duality bounds the MAX arg
// (<= ~96, verified by R9's never-firing window check); tails can be arbitrarily negative and
// are flushed to zero by the guarded poly / by ex2 underflow.
// Exponentials split: rows 0-1 on MUFU (ex2), rows 2-3 on the fma pipe (guarded packed poly).
// DIR==0: rows = noise(x), tile = x0(y) -> writes cX; DIR==1: rows = x0(y), tile = noise(x) -> g, cY
template <int DIR>
__global__ void __launch_bounds__(256, 3) k_half(float eps, float ie2 /* (1/eps)*log2(e) */) {
    __shared__ __align__(16) ulonglong2 sXY[NPT/4], sZC[NPT/4];
    __shared__ int sWin;
    const int b = blockIdx.y;
    const int base = b * NPT;
    const int rowblock = blockIdx.x >> 1;
    const int jhalf = blockIdx.x & 1;
    const float4* __restrict__ vxy = (DIR ? g_xyX : g_xyY) + (base >> 1) + jhalf * (NPT / 4);
    const float4* __restrict__ vzc = (DIR ? g_zcX : g_zcY) + (base >> 1) + jhalf * (NPT / 4);
    const float4* __restrict__ Pq  = DIR ? g_yp : g_xp;
    const float*  __restrict__ rowzc = (const float*)(DIR ? g_zcY : g_zcX);

    const int tid = threadIdx.x;
    {
        float4* dxy = (float4*)sXY; float4* dzc = (float4*)sZC;
#pragma unroll
        for (int j = tid; j < NPT / 4; j += 256) { dxy[j] = vxy[j]; dzc[j] = vzc[j]; }
    }
    __syncthreads();

    const int warp = tid >> 5, lane = tid & 31;
    const int r0 = rowblock * 32 + warp * 4;

    u64 qx2[4], qy2[4], qz2[4], K[4];
#pragma unroll
    for (int k = 0; k < 4; k++) {
        float4 q = Pq[base + r0 + k];
        qx2[k] = pk2(q.x, q.x);
        qy2[k] = pk2(q.y, q.y);
        qz2[k] = pk2(q.z, q.z);
        float crow = rowzc[(((base + r0) >> 1) + (k >> 1)) * 4 + 2 + (k & 1)];
        float khat = __fmul_rn(crow, ie2);
        K[k] = pk2(khat, khat);
    }
    const u64 IE2P = pk2(ie2, ie2);
    // poly constants (hoisted)
    const u64 MAG  = pk2(12582912.0f, 12582912.0f);    // 1.5*2^23
    const u64 NMAG = pk2(-12582912.0f, -12582912.0f);
    const u64 C6 = pk2(1.535336188319500e-4f, 1.535336188319500e-4f);
    const u64 C5 = pk2(1.339887440266574e-3f, 1.339887440266574e-3f);
    const u64 C4 = pk2(9.618437357674640e-3f, 9.618437357674640e-3f);
    const u64 C3 = pk2(5.550332471162809e-2f, 5.550332471162809e-2f);
    const u64 C2 = pk2(2.402264791363012e-1f, 2.402264791363012e-1f);
    const u64 C1 = pk2(6.931472028550421e-1f, 6.931472028550421e-1f);

    float a0l = 0.f, a0h = 0.f, a1l = 0.f, a1h = 0.f;
    u64 A2 = pk2(0.f, 0.f), A3 = pk2(0.f, 0.f);

#pragma unroll 2
    for (int it = 0; it < NPT / 128; ++it) {
        const int jj = lane + it * 32;
        const ulonglong2 pxy = sXY[jj];
        const ulonglong2 pzc = sZC[jj];
        u64 t0 = fma2_(qz2[0], pzc.x, fma2_(qy2[0], pxy.y, fma2_(qx2[0], pxy.x, pzc.y)));
        u64 t1 = fma2_(qz2[1], pzc.x, fma2_(qy2[1], pxy.y, fma2_(qx2[1], pxy.x, pzc.y)));
        u64 t2 = fma2_(qz2[2], pzc.x, fma2_(qy2[2], pxy.y, fma2_(qx2[2], pxy.x, pzc.y)));
        u64 t3 = fma2_(qz2[3], pzc.x, fma2_(qy2[3], pxy.y, fma2_(qx2[3], pxy.x, pzc.y)));
        u64 ea0 = fma2_(IE2P, t0, K[0]);
        u64 ea1 = fma2_(IE2P, t1, K[1]);
        u64 ea2 = fma2_(IE2P, t2, K[2]);
        u64 ea3 = fma2_(IE2P, t3, K[3]);
        // rows 0,1: MUFU path
        float e0l, e0h, e1l, e1h;
        up2(ea0, e0l, e0h); up2(ea1, e1l, e1h);
        a0l += ex2_(e0l); a0h += ex2_(e0h);
        a1l += ex2_(e1l); a1h += ex2_(e1h);
        // rows 2,3: fma-pipe guarded packed poly path
        A2 = add2_(A2, exp2p2(ea2, MAG, NMAG, C6, C5, C4, C3, C2, C1));
        A3 = add2_(A3, exp2p2(ea3, MAG, NMAG, C6, C5, C4, C3, C2, C1));
    }

    float s[4];
    s[0] = __fadd_rn(a0l, a0h);
    s[1] = __fadd_rn(a1l, a1h);
    { float x, y; up2(A2, x, y); s[2] = __fadd_rn(x, y); }
    { float x, y; up2(A3, x, y); s[3] = __fadd_rn(x, y); }

#pragma unroll
    for (int k = 0; k < 4; k++) {
        float a = s[k];
#pragma unroll
        for (int o = 16; o; o >>= 1) a += __shfl_xor_sync(0xffffffffu, a, o);
        if (lane == 0) atomicAdd(&g_acc[base + r0 + k], a);
    }

    __syncthreads();
    if (tid == 0) {
        __threadfence();
        int o = atomicAdd(&g_cnt[b * 64 + rowblock], 1);
        sWin = (o == 1);
    }
    __syncthreads();

    if (sWin && warp == 0) {
        __threadfence();   // acquire: sibling's partial adds visible
        const int row = base + rowblock * 32 + lane;
        float S = g_acc[row];
        g_acc[row] = 0.f;
        const int pr4 = (row >> 1) * 4 + 2 + (row & 1);
        float crow = rowzc[pr4];
        float khat = __fmul_rn(crow, ie2);
        float base2 = __fadd_rn(LOGC2, -khat);
        float cnew = __fmul_rn(-eps, fmaf(base2, LN2F, logf(S)));
        if (DIR == 0) {
            ((float*)g_zcX)[pr4] = cnew;                        // f - 0.5|x|^2
        } else {
            g_g[row] = fmaf(0.5f, g_yp[row].w, cnew);           // g (for argmin)
            ((float*)g_zcY)[pr4] = cnew;                        // g - 0.5|y|^2
        }
        if (lane == 0) g_cnt[b * 64 + rowblock] = 0;
    }
}

// ---------------- argmin over m of (sqdist - g_m), first-index ties ----------------
__global__ void __launch_bounds__(256) k_argmin() {
    __shared__ float4 sp[NPT];
    __shared__ float  sg[NPT];
    const int b = blockIdx.y;
    const int base = b * NPT;
    const int tid = threadIdx.x;
    for (int j = tid; j < NPT; j += 256) { sp[j] = g_yp[base + j]; sg[j] = g_g[base + j]; }
    __syncthreads();
    const int warp = tid >> 5, lane = tid & 31;
    const int r0 = blockIdx.x * 32 + warp * 4;

    float qx[4], qy[4], qz[4], qn[4];
#pragma unroll
    for (int k = 0; k < 4; k++) {
        float4 q = g_xp[base + r0 + k];
        qx[k] = q.x; qy[k] = q.y; qz[k] = q.z; qn[k] = q.w;
    }
    float bv[4] = {INFINITY, INFINITY, INFINITY, INFINITY};
    int   bi[4] = {0, 0, 0, 0};
#pragma unroll 2
    for (int j = lane; j < NPT; j += 32) {
        const float4 p = sp[j];
        const float gg = sg[j];
#pragma unroll
        for (int k = 0; k < 4; k++) {
            float d = fmaf(qz[k], p.z, fmaf(qy[k], p.y, __fmul_rn(qx[k], p.x)));
            float s = fmaf(-2.f, d, __fadd_rn(qn[k], p.w));
            s = fmaxf(s, 0.f);
            float v = __fadd_rn(s, -gg);
            if (v < bv[k]) { bv[k] = v; bi[k] = j; }
        }
    }
#pragma unroll
    for (int k = 0; k < 4; k++) {
#pragma unroll
        for (int o = 16; o; o >>= 1) {
            float v2 = __shfl_xor_sync(0xffffffffu, bv[k], o);
            int   i2 = __shfl_xor_sync(0xffffffffu, bi[k], o);
            if (v2 < bv[k] || (v2 == bv[k] && i2 < bi[k])) { bv[k] = v2; bi[k] = i2; }
        }
    }
    if (lane == 0) {
#pragma unroll
        for (int k = 0; k < 4; k++) g_idx[base + r0 + k] = bi[k];
    }
}

// ---------------- gather + MLP head, write (v_pred, v) ----------------
__global__ void __launch_bounds__(256) k_mlp(const float* __restrict__ noise, const float* __restrict__ tt,
                                             const float* __restrict__ W1, const float* __restrict__ Wt,
                                             const float* __restrict__ b1, const float* __restrict__ W2,
                                             const float* __restrict__ b2, float* __restrict__ out) {
    __shared__ float sW1[3 * HID], sW2[HID * 3], sWt[HID], sb1[HID];
    const int tid = threadIdx.x;
    for (int i = tid; i < 3 * HID; i += 256) { sW1[i] = W1[i]; sW2[i] = W2[i]; }
    for (int i = tid; i < HID; i += 256) { sWt[i] = Wt[i]; sb1[i] = b1[i]; }
    __syncthreads();

    const int p = blockIdx.x * 256 + tid;
    const int b = p >> 11;
    const float t = tt[b];
    const int id = g_idx[p];
    const float4 y = g_yp[(b << 11) + id];
    const float n0 = noise[p * 3 + 0], n1 = noise[p * 3 + 1], n2 = noise[p * 3 + 2];
    const float v0 = __fadd_rn(n0, -y.x);
    const float v1 = __fadd_rn(n1, -y.y);
    const float v2 = __fadd_rn(n2, -y.z);
    const float omt = __fadd_rn(1.f, -t);
    const float x0t = __fadd_rn(__fmul_rn(omt, y.x), __fmul_rn(t, n0));
    const float x1t = __fadd_rn(__fmul_rn(omt, y.y), __fmul_rn(t, n1));
    const float x2t = __fadd_rn(__fmul_rn(omt, y.z), __fmul_rn(t, n2));

    float a0 = b2[0], a1 = b2[1], a2 = b2[2];
#pragma unroll 8
    for (int j = 0; j < HID; j++) {
        float h = fmaf(x2t, sW1[2 * HID + j], fmaf(x1t, sW1[HID + j], __fmul_rn(x0t, sW1[j])));
        h = __fadd_rn(__fadd_rn(h, __fmul_rn(t, sWt[j])), sb1[j]);
        h = fmaxf(h, 0.f);
        a0 = fmaf(h, sW2[j * 3 + 0], a0);
        a1 = fmaf(h, sW2[j * 3 + 1], a1);
        a2 = fmaf(h, sW2[j * 3 + 2], a2);
    }
    out[p * 3 + 0] = a0;
    out[p * 3 + 1] = a1;
    out[p * 3 + 2] = a2;
    out[NTOT * 3 + p * 3 + 0] = v0;
    out[NTOT * 3 + p * 3 + 1] = v1;
    out[NTOT * 3 + p * 3 + 2] = v2;
}

// ---------------- launcher ----------------
extern "C" void kernel_launch(void* const* d_in, const int* in_sizes, int n_in,
                              void* d_out, int out_size) {
    const float* cloud = (const float*)d_in[0];
    const float* noise = (const float*)d_in[1];
    const float* t     = (const float*)d_in[2];
    const float* W1    = (const float*)d_in[3];
    const float* Wt    = (const float*)d_in[4];
    const float* b1    = (const float*)d_in[5];
    const float* W2    = (const float*)d_in[6];
    const float* b2    = (const float*)d_in[7];
    float* out = (float*)d_out;

    k_std<<<BB, 256>>>(cloud);
    k_pack<<<NTOT / 256, 256>>>(cloud, noise);

    // EPS_LIST = np.geomspace(32.0, 0.001**2, 14).astype(np.float32)
    const double blur2 = 0.001 * 0.001;
    const double l0 = log10(32.0);
    const double l1 = log10(blur2);
    const double step = (l1 - l0) / (double)(NITER - 1);
    const double LOG2E = 1.4426950408889634;
    const dim3 gridH((NPT / 32) * 2, BB);   // rowblocks x 2 j-halves -> 1024 blocks
    const dim3 gridA(NPT / 32, BB);

    for (int it = 0; it < NITER; it++) {
        double ev;
        if (it == 0)              ev = 32.0;
        else if (it == NITER - 1) ev = blur2;
        else                      ev = pow(10.0, l0 + (double)it * step);
        const float eps = (float)ev;
        const float ie2 = (float)((double)(1.0f / eps) * LOG2E);
        k_half<0><<<gridH, 256>>>(eps, ie2);  // f-update
        k_half<1><<<gridH, 256>>>(eps, ie2);  // g-update
    }

    k_argmin<<<gridA, 256>>>();
    k_mlp<<<NTOT / 256, 256>>>(noise, t, W1, Wt, b1, W2, b2, out);

    (void)in_sizes; (void)n_in; (void)out_size;
}

// round 13
// speedup vs baseline: 1.1987x; 1.1987x over previous
#include <cuda_runtime.h>
#include <math.h>

#define BB  8
#define NPT 2048
#define NTOT (BB*NPT)
#define HID 256
#define NITER 14

typedef unsigned long long u64;

// ---------------- f32x2 packed helpers (sm_103a) ----------------
__device__ __forceinline__ u64 pk2(float lo, float hi) {
    u64 r; asm("mov.b64 %0,{%1,%2};" : "=l"(r) : "f"(lo), "f"(hi)); return r;
}
__device__ __forceinline__ void up2(u64 v, float& lo, float& hi) {
    asm("mov.b64 {%0,%1},%2;" : "=f"(lo), "=f"(hi) : "l"(v));
}
__device__ __forceinline__ u64 fma2_(u64 a, u64 b, u64 c) {
    u64 r; asm("fma.rn.f32x2 %0,%1,%2,%3;" : "=l"(r) : "l"(a), "l"(b), "l"(c)); return r;
}
__device__ __forceinline__ float ex2_(float x) {
    float r; asm("ex2.approx.f32 %0,%1;" : "=f"(r) : "f"(x)); return r;
}

// ---------------- persistent scratch ----------------
__device__ float4 g_xp[NTOT];   // noise points packed: (x,y,z,|x|^2)
__device__ float4 g_yp[NTOT];   // x0 points packed:    (x,y,z,|y|^2)
// interleaved pair tiles for k_half reduce side:
//   g_xy*[pair] = (x_{2j}, x_{2j+1}, y_{2j}, y_{2j+1})
//   g_zc*[pair] = (z_{2j}, z_{2j+1}, c_{2j}, c_{2j+1}),  c = phi - 0.5*|p|^2
__device__ float4 g_xyX[NTOT/2], g_zcX[NTOT/2];   // X side (noise)
__device__ float4 g_xyY[NTOT/2], g_zcY[NTOT/2];   // Y side (x0)
__device__ float  g_g[NTOT];
__device__ float  g_std[BB];
__device__ int    g_idx[NTOT];
// j-split partial-sum machinery
__device__ float  g_acc[NTOT];     // per-row partial sum accumulator (zero outside launches)
__device__ int    g_cnt[BB * 64];  // per (batch, rowblock) arrival counter

// ---------------- per-batch std (ddof=1) ----------------
__global__ void k_std(const float* __restrict__ cloud) {
    __shared__ float red[256];
    const int b = blockIdx.x;
    const float* p = cloud + b * NPT * 3;
    const int tid = threadIdx.x;
    float s = 0.f;
    for (int i = tid; i < NPT * 3; i += 256) s += p[i];
    red[tid] = s; __syncthreads();
    for (int o = 128; o > 0; o >>= 1) { if (tid < o) red[tid] += red[tid + o]; __syncthreads(); }
    const float mean = red[0] / (float)(NPT * 3);
    __syncthreads();
    float s2 = 0.f;
    for (int i = tid; i < NPT * 3; i += 256) { float d = p[i] - mean; s2 = fmaf(d, d, s2); }
    red[tid] = s2; __syncthreads();
    for (int o = 128; o > 0; o >>= 1) { if (tid < o) red[tid] += red[tid + o]; __syncthreads(); }
    if (tid == 0) g_std[b] = sqrtf(red[0] / (float)(NPT * 3 - 1));
}

// ---------------- pack points, build interleaved tiles, init folded constants ----------------
__global__ void k_pack(const float* __restrict__ cloud, const float* __restrict__ noise) {
    int i = blockIdx.x * blockDim.x + threadIdx.x;
    if (i >= NTOT) return;
    int b = i >> 11;
    float sd = g_std[b];
    float c0 = cloud[i * 3 + 0] / sd;
    float c1 = cloud[i * 3 + 1] / sd;
    float c2 = cloud[i * 3 + 2] / sd;
    float yn = __fadd_rn(__fadd_rn(__fmul_rn(c0, c0), __fmul_rn(c1, c1)), __fmul_rn(c2, c2));
    g_yp[i] = make_float4(c0, c1, c2, yn);
    float n0 = noise[i * 3 + 0], n1 = noise[i * 3 + 1], n2 = noise[i * 3 + 2];
    float xn = __fadd_rn(__fadd_rn(__fmul_rn(n0, n0), __fmul_rn(n1, n1)), __fmul_rn(n2, n2));
    g_xp[i] = make_float4(n0, n1, n2, xn);

    const int pr = i >> 1, h = i & 1;
    float* fxyX = (float*)g_xyX; float* fzcX = (float*)g_zcX;
    float* fxyY = (float*)g_xyY; float* fzcY = (float*)g_zcY;
    fxyX[pr * 4 + h]     = n0;
    fxyX[pr * 4 + 2 + h] = n1;
    fzcX[pr * 4 + h]     = n2;
    fzcX[pr * 4 + 2 + h] = __fmul_rn(-0.5f, xn);   // phi==0 -> c = -0.5|x|^2
    fxyY[pr * 4 + h]     = c0;
    fxyY[pr * 4 + 2 + h] = c1;
    fzcY[pr * 4 + h]     = c2;
    fzcY[pr * 4 + 2 + h] = __fmul_rn(-0.5f, yn);

    g_acc[i] = 0.f;
    if (i < BB * 64) g_cnt[i] = 0;
}

// log2(1/2048) is exactly -11
#define LOGC2 (-11.0f)
#define LN2F  (0.6931471805599453f)

// ---------------- one Sinkhorn half-update: single pass, duality shift, j-split x4 ----------------
// arg(i,j) = (q_i.p_j + c_j)*ie2 + khat_i,  khat_i = c_row_i*ie2. Duality bounds the MAX arg
// (<= ~96 < fp32 overflow 117), so no max pass is needed; tails underflow ex2 to 0 harmlessly.
// Grid: blockIdx.x = rowblock*4 + jquarter (256), blockIdx.y = batch. Each block sums its
// quarter of j; partials combine via atomicAdd; 4th-arriving block finalizes.
// DIR==0: rows = noise(x), tile = x0(y) -> writes cX; DIR==1: rows = x0(y), tile = noise(x) -> g, cY
template <int DIR>
__global__ void __launch_bounds__(256, 5) k_half(float eps, float ie2 /* (1/eps)*log2(e) */) {
    __shared__ __align__(16) ulonglong2 sXY[NPT/8], sZC[NPT/8];
    __shared__ int sWin;
    const int b = blockIdx.y;
    const int base = b * NPT;
    const int rowblock = blockIdx.x >> 2;
    const int jq = blockIdx.x & 3;
    const float4* __restrict__ vxy = (DIR ? g_xyX : g_xyY) + (base >> 1) + jq * (NPT / 8);
    const float4* __restrict__ vzc = (DIR ? g_zcX : g_zcY) + (base >> 1) + jq * (NPT / 8);
    const float4* __restrict__ Pq  = DIR ? g_yp : g_xp;
    const float*  __restrict__ rowzc = (const float*)(DIR ? g_zcY : g_zcX);

    const int tid = threadIdx.x;
    {
        float4* dxy = (float4*)sXY; float4* dzc = (float4*)sZC;
        if (tid < NPT / 8) { dxy[tid] = vxy[tid]; dzc[tid] = vzc[tid]; }
    }
    __syncthreads();

    const int warp = tid >> 5, lane = tid & 31;
    const int r0 = rowblock * 32 + warp * 4;

    u64 qx2[4], qy2[4], qz2[4], K[4];
#pragma unroll
    for (int k = 0; k < 4; k++) {
        float4 q = Pq[base + r0 + k];
        qx2[k] = pk2(q.x, q.x);
        qy2[k] = pk2(q.y, q.y);
        qz2[k] = pk2(q.z, q.z);
        float crow = rowzc[(((base + r0) >> 1) + (k >> 1)) * 4 + 2 + (k & 1)];
        float khat = __fmul_rn(crow, ie2);
        K[k] = pk2(khat, khat);
    }
    const u64 IE2P = pk2(ie2, ie2);

    float aL[4] = {0.f, 0.f, 0.f, 0.f};
    float aH[4] = {0.f, 0.f, 0.f, 0.f};

#pragma unroll 4
    for (int it = 0; it < NPT / 256; ++it) {
        const int jj = lane + it * 32;
        const ulonglong2 pxy = sXY[jj];
        const ulonglong2 pzc = sZC[jj];
#pragma unroll
        for (int k = 0; k < 4; k++) {
            u64 t  = fma2_(qz2[k], pzc.x, fma2_(qy2[k], pxy.y, fma2_(qx2[k], pxy.x, pzc.y)));
            u64 ea = fma2_(IE2P, t, K[k]);
            float el, eh; up2(ea, el, eh);
            aL[k] += ex2_(el);
            aH[k] += ex2_(eh);
        }
    }

#pragma unroll
    for (int k = 0; k < 4; k++) {
        float a = __fadd_rn(aL[k], aH[k]);
#pragma unroll
        for (int o = 16; o; o >>= 1) a += __shfl_xor_sync(0xffffffffu, a, o);
        if (lane == 0) atomicAdd(&g_acc[base + r0 + k], a);
    }

    __syncthreads();
    if (tid == 0) {
        __threadfence();
        int o = atomicAdd(&g_cnt[b * 64 + rowblock], 1);
        sWin = (o == 3);
    }
    __syncthreads();

    if (sWin && warp == 0) {
        __threadfence();   // acquire: sibling partial adds visible
        const int row = base + rowblock * 32 + lane;
        float S = g_acc[row];
        g_acc[row] = 0.f;
        const int pr4 = (row >> 1) * 4 + 2 + (row & 1);
        float crow = rowzc[pr4];
        float khat = __fmul_rn(crow, ie2);
        float base2 = __fadd_rn(LOGC2, -khat);
        float cnew = __fmul_rn(-eps, fmaf(base2, LN2F, logf(S)));
        if (DIR == 0) {
            ((float*)g_zcX)[pr4] = cnew;                        // f - 0.5|x|^2
        } else {
            g_g[row] = fmaf(0.5f, g_yp[row].w, cnew);           // g (for argmin)
            ((float*)g_zcY)[pr4] = cnew;                        // g - 0.5|y|^2
        }
        if (lane == 0) g_cnt[b * 64 + rowblock] = 0;
    }
}

// ---------------- argmin over m of (sqdist - g_m), first-index ties ----------------
__global__ void __launch_bounds__(256) k_argmin() {
    __shared__ float4 sp[NPT];
    __shared__ float  sg[NPT];
    const int b = blockIdx.y;
    const int base = b * NPT;
    const int tid = threadIdx.x;
    for (int j = tid; j < NPT; j += 256) { sp[j] = g_yp[base + j]; sg[j] = g_g[base + j]; }
    __syncthreads();
    const int warp = tid >> 5, lane = tid & 31;
    const int r0 = blockIdx.x * 32 + warp * 4;

    float qx[4], qy[4], qz[4], qn[4];
#pragma unroll
    for (int k = 0; k < 4; k++) {
        float4 q = g_xp[base + r0 + k];
        qx[k] = q.x; qy[k] = q.y; qz[k] = q.z; qn[k] = q.w;
    }
    float bv[4] = {INFINITY, INFINITY, INFINITY, INFINITY};
    int   bi[4] = {0, 0, 0, 0};
#pragma unroll 2
    for (int j = lane; j < NPT; j += 32) {
        const float4 p = sp[j];
        const float gg = sg[j];
#pragma unroll
        for (int k = 0; k < 4; k++) {
            float d = fmaf(qz[k], p.z, fmaf(qy[k], p.y, __fmul_rn(qx[k], p.x)));
            float s = fmaf(-2.f, d, __fadd_rn(qn[k], p.w));
            s = fmaxf(s, 0.f);
            float v = __fadd_rn(s, -gg);
            if (v < bv[k]) { bv[k] = v; bi[k] = j; }
        }
    }
#pragma unroll
    for (int k = 0; k < 4; k++) {
#pragma unroll
        for (int o = 16; o; o >>= 1) {
            float v2 = __shfl_xor_sync(0xffffffffu, bv[k], o);
            int   i2 = __shfl_xor_sync(0xffffffffu, bi[k], o);
            if (v2 < bv[k] || (v2 == bv[k] && i2 < bi[k])) { bv[k] = v2; bi[k] = i2; }
        }
    }
    if (lane == 0) {
#pragma unroll
        for (int k = 0; k < 4; k++) g_idx[base + r0 + k] = bi[k];
    }
}

// ---------------- gather + MLP head, write (v_pred, v) ----------------
__global__ void __launch_bounds__(256) k_mlp(const float* __restrict__ noise, const float* __restrict__ tt,
                                             const float* __restrict__ W1, const float* __restrict__ Wt,
                                             const float* __restrict__ b1, const float* __restrict__ W2,
                                             const float* __restrict__ b2, float* __restrict__ out) {
    __shared__ float sW1[3 * HID], sW2[HID * 3], sWt[HID], sb1[HID];
    const int tid = threadIdx.x;
    for (int i = tid; i < 3 * HID; i += 256) { sW1[i] = W1[i]; sW2[i] = W2[i]; }
    for (int i = tid; i < HID; i += 256) { sWt[i] = Wt[i]; sb1[i] = b1[i]; }
    __syncthreads();

    const int p = blockIdx.x * 256 + tid;
    const int b = p >> 11;
    const float t = tt[b];
    const int id = g_idx[p];
    const float4 y = g_yp[(b << 11) + id];
    const float n0 = noise[p * 3 + 0], n1 = noise[p * 3 + 1], n2 = noise[p * 3 + 2];
    const float v0 = __fadd_rn(n0, -y.x);
    const float v1 = __fadd_rn(n1, -y.y);
    const float v2 = __fadd_rn(n2, -y.z);
    const float omt = __fadd_rn(1.f, -t);
    const float x0t = __fadd_rn(__fmul_rn(omt, y.x), __fmul_rn(t, n0));
    const float x1t = __fadd_rn(__fmul_rn(omt, y.y), __fmul_rn(t, n1));
    const float x2t = __fadd_rn(__fmul_rn(omt, y.z), __fmul_rn(t, n2));

    float a0 = b2[0], a1 = b2[1], a2 = b2[2];
#pragma unroll 8
    for (int j = 0; j < HID; j++) {
        float h = fmaf(x2t, sW1[2 * HID + j], fmaf(x1t, sW1[HID + j], __fmul_rn(x0t, sW1[j])));
        h = __fadd_rn(__fadd_rn(h, __fmul_rn(t, sWt[j])), sb1[j]);
        h = fmaxf(h, 0.f);
        a0 = fmaf(h, sW2[j * 3 + 0], a0);
        a1 = fmaf(h, sW2[j * 3 + 1], a1);
        a2 = fmaf(h, sW2[j * 3 + 2], a2);
    }
    out[p * 3 + 0] = a0;
    out[p * 3 + 1] = a1;
    out[p * 3 + 2] = a2;
    out[NTOT * 3 + p * 3 + 0] = v0;
    out[NTOT * 3 + p * 3 + 1] = v1;
    out[NTOT * 3 + p * 3 + 2] = v2;
}

// ---------------- launcher ----------------
extern "C" void kernel_launch(void* const* d_in, const int* in_sizes, int n_in,
                              void* d_out, int out_size) {
    const float* cloud = (const float*)d_in[0];
    const float* noise = (const float*)d_in[1];
    const float* t     = (const float*)d_in[2];
    const float* W1    = (const float*)d_in[3];
    const float* Wt    = (const float*)d_in[4];
    const float* b1    = (const float*)d_in[5];
    const float* W2    = (const float*)d_in[6];
    const float* b2    = (const float*)d_in[7];
    float* out = (float*)d_out;

    k_std<<<BB, 256>>>(cloud);
    k_pack<<<NTOT / 256, 256>>>(cloud, noise);

    // EPS_LIST = np.geomspace(32.0, 0.001**2, 14).astype(np.float32)
    const double blur2 = 0.001 * 0.001;
    const double l0 = log10(32.0);
    const double l1 = log10(blur2);
    const double step = (l1 - l0) / (double)(NITER - 1);
    const double LOG2E = 1.4426950408889634;
    const dim3 gridH((NPT / 32) * 4, BB);   // rowblocks x 4 j-quarters -> 2048 blocks
    const dim3 gridA(NPT / 32, BB);

    for (int it = 0; it < NITER; it++) {
        double ev;
        if (it == 0)              ev = 32.0;
        else if (it == NITER - 1) ev = blur2;
        else                      ev = pow(10.0, l0 + (double)it * step);
        const float eps = (float)ev;
        const float ie2 = (float)((double)(1.0f / eps) * LOG2E);
        k_half<0><<<gridH, 256>>>(eps, ie2);  // f-update
        k_half<1><<<gridH, 256>>>(eps, ie2);  // g-update
    }

    k_argmin<<<gridA, 256>>>();
    k_mlp<<<NTOT / 256, 256>>>(noise, t, W1, Wt, b1, W2, b2, out);

    (void)in_sizes; (void)n_in; (void)out_size;
}